// round 10
// baseline (speedup 1.0000x reference)
#include <cuda_runtime.h>
#include <cuda.h>
#include <cstdint>
#include <math.h>

#define D 768
#define B 512
#define NTOT (2 * D)            // 1536 rows of concatenated W

// GEMM tiling: CTA 128x128, 256 threads, warp tile 64x32; TK=128 int8/stage
#define TM 128
#define TN 128
#define TK 128                  // int8 K elements per chunk (128 B smem row)
#define STAGES 4
#define CHUNKS_PER (D / TK)     // 6
#define NCTA 144                // (12, 4, 3)
#define NTHREADS 256

#define STAGE_BYTES 32768       // A 16KB + B 16KB
#define SMEM_MBAR_OFF 640       // full[4] @640, empty[4] @672
#define SMEM_TILES_OFF 1024
#define SMEM_TOTAL (SMEM_TILES_OFF + STAGES * STAGE_BYTES)   // 132096 -> 1 CTA/SM

#define QMAX 32639              // 2-limb s8 range with (q+128)>>8 split

// ---------------------------------------------------------------------------
// Device scratch (allocation-free)
// ---------------------------------------------------------------------------
__device__ int8_t g_s_hi[B * D];
__device__ int8_t g_s_lo[B * D];
__device__ int8_t g_W_hi[NTOT * D];
__device__ int8_t g_W_lo[NTOT * D];
__device__ float  g_sscale[B];      // rowmax/QMAX  (inverse quant scale)
__device__ float  g_wscale[NTOT];
__device__ float  g_logits[B * 2];
__device__ int    g_sync;

// ---------------------------------------------------------------------------
// PTX helpers (sm_80/sm_90 base features — legal on plain compute_103)
// ---------------------------------------------------------------------------
__device__ __forceinline__ uint32_t smem_u32(const void* p) {
    uint32_t a;
    asm("{ .reg .u64 t; cvta.to.shared.u64 t, %1; cvt.u32.u64 %0, t; }"
        : "=r"(a) : "l"(p));
    return a;
}

#define SWZ(o) ((o) ^ (((o) >> 3) & 0x70))

#define MBARRIER_INIT(addr, cnt) \
    asm volatile("mbarrier.init.shared.b64 [%0], %1;" :: "r"(addr), "r"(cnt) : "memory")
#define MBARRIER_EXPECT_TX(addr, bytes) \
    asm volatile("mbarrier.arrive.expect_tx.shared.b64 _, [%0], %1;" \
                 :: "r"(addr), "r"(bytes) : "memory")
#define MBARRIER_ARRIVE(addr) \
    asm volatile("mbarrier.arrive.shared.b64 _, [%0];" :: "r"(addr) : "memory")

__device__ __forceinline__ void mbar_wait(uint32_t mbar, uint32_t parity) {
    uint32_t done;
    asm volatile("{\n\t.reg .pred p;\n\t"
                 "mbarrier.try_wait.parity.acquire.cta.shared::cta.b64 p, [%1], %2;\n\t"
                 "selp.b32 %0, 1, 0, p;\n\t}"
                 : "=r"(done) : "r"(mbar), "r"(parity) : "memory");
    if (!done) {
        asm volatile("{\n\t.reg .pred P1;\n\t"
                     "WL_%=:\n\t"
                     "mbarrier.try_wait.parity.acquire.cta.shared::cta.b64 P1, [%0], %1, 0x989680;\n\t"
                     "@P1 bra.uni WD_%=;\n\t"
                     "bra.uni WL_%=;\n\t"
                     "WD_%=:\n\t}"
                     :: "r"(mbar), "r"(parity) : "memory");
    }
}

__device__ __forceinline__ void tma_load_2d(uint32_t dst, const CUtensorMap* map,
                                            int x, int y, uint32_t mbar) {
    asm volatile("cp.async.bulk.tensor.2d.shared::cta.global.tile.mbarrier::complete_tx::bytes "
                 "[%0], [%1, {%2, %3}], [%4];"
                 :: "r"(dst), "l"(map), "r"(x), "r"(y), "r"(mbar) : "memory");
}

#define LDSM_X4(r, addr) \
    asm volatile("ldmatrix.sync.aligned.m8n8.x4.shared.b16 {%0,%1,%2,%3}, [%4];" \
                 : "=r"((r)[0]), "=r"((r)[1]), "=r"((r)[2]), "=r"((r)[3]) \
                 : "r"(addr))

// int8 IMMA, K=32 per instruction, s32 accumulators
#define MMA_S8(d, a, b0, b1) \
    asm volatile("mma.sync.aligned.m16n8k32.row.col.s32.s8.s8.s32 " \
                 "{%0,%1,%2,%3}, {%4,%5,%6,%7}, {%8,%9}, {%0,%1,%2,%3};" \
                 : "+r"((d)[0]), "+r"((d)[1]), "+r"((d)[2]), "+r"((d)[3]) \
                 : "r"((a)[0]), "r"((a)[1]), "r"((a)[2]), "r"((a)[3]), \
                   "r"(b0), "r"(b1))

// ---------------------------------------------------------------------------
// Kernel 1: per-row 16-bit fixed-point quantization into 2 x s8 limbs.
// One block per row (W rows first, then s rows). 192 threads x 4 elems.
// Also: logits = bias (blocks 0-5), g_sync = 0 (block 0).
// ---------------------------------------------------------------------------
__global__ __launch_bounds__(192)
void quant_kernel(const float4* __restrict__ W4p,
                  const float4* __restrict__ S4p,
                  const float* __restrict__ fc_b) {
    __shared__ float red[8];
    const int row = blockIdx.x;
    const int tid = threadIdx.x;

    if (row == 0 && tid == 0) g_sync = 0;
    if (row < 6) {
        int idx = row * 192 + tid;
        if (idx < B * 2) g_logits[idx] = fc_b[idx & 1];
    }

    const bool isW = (row < NTOT);
    const float4* src = isW ? (W4p + (size_t)row * (D / 4))
                            : (S4p + (size_t)(row - NTOT) * (D / 4));
    float4 x = src[tid];

    // row max |x|
    float m = fmaxf(fmaxf(fabsf(x.x), fabsf(x.y)), fmaxf(fabsf(x.z), fabsf(x.w)));
#pragma unroll
    for (int off = 16; off > 0; off >>= 1)
        m = fmaxf(m, __shfl_xor_sync(0xffffffff, m, off));
    if ((tid & 31) == 0) red[tid >> 5] = m;
    __syncthreads();
    if (tid == 0) {
        float rm = red[0];
#pragma unroll
        for (int w = 1; w < 6; w++) rm = fmaxf(rm, red[w]);
        rm = fmaxf(rm, 1e-30f);
        red[6] = (float)QMAX / rm;      // quant scale
        red[7] = rm / (float)QMAX;      // inverse (dequant) scale
    }
    __syncthreads();
    const float sc = red[6];

    int q[4];
    float v[4] = {x.x, x.y, x.z, x.w};
#pragma unroll
    for (int j = 0; j < 4; j++) {
        int qq = __float2int_rn(v[j] * sc);
        q[j] = min(max(qq, -QMAX), QMAX);
    }
    char4 hi, lo;
    int h0 = (q[0] + 128) >> 8, h1 = (q[1] + 128) >> 8,
        h2 = (q[2] + 128) >> 8, h3 = (q[3] + 128) >> 8;
    hi = make_char4((char)h0, (char)h1, (char)h2, (char)h3);
    lo = make_char4((char)(q[0] - (h0 << 8)), (char)(q[1] - (h1 << 8)),
                    (char)(q[2] - (h2 << 8)), (char)(q[3] - (h3 << 8)));

    if (isW) {
        *(char4*)(g_W_hi + (size_t)row * D + tid * 4) = hi;
        *(char4*)(g_W_lo + (size_t)row * D + tid * 4) = lo;
        if (tid == 0) g_wscale[row] = red[7];
    } else {
        int r2 = row - NTOT;
        *(char4*)(g_s_hi + (size_t)r2 * D + tid * 4) = hi;
        *(char4*)(g_s_lo + (size_t)r2 * D + tid * 4) = lo;
        if (tid == 0) g_sscale[r2] = red[7];
    }
}

// ---------------------------------------------------------------------------
// Fragment loaders (SW128-swizzled LDSM; identical addressing to bf16 —
// 16-byte columns are now 16 int8 K-values)
// ---------------------------------------------------------------------------
__device__ __forceinline__ void ldsm_a(uint32_t sA, int warp_m, int rowA,
                                       int colSelA, int ks, uint32_t af[4][4]) {
#pragma unroll
    for (int mi = 0; mi < 4; mi++) {
        uint32_t addr = sA + SWZ((64 * warp_m + 16 * mi + rowA) * 128
                                 + (2 * ks + colSelA) * 16);
        LDSM_X4(af[mi], addr);
    }
}
__device__ __forceinline__ void ldsm_b(uint32_t sB, int warp_n, int rowB,
                                       int colSelB, int ks, uint32_t bfr[2][4]) {
#pragma unroll
    for (int q = 0; q < 2; q++) {
        uint32_t addr = sB + SWZ((32 * warp_n + 16 * q + rowB) * 128
                                 + (2 * ks + colSelB) * 16);
        LDSM_X4(bfr[q], addr);
    }
}

// ---------------------------------------------------------------------------
// Kernel 2: TMA-fed IMMA s8 GEMM (m16n8k32) + scale-unwinding v-dot reduce +
// device-wide barrier + softmax/fuse. Grid (12, 4, 3) = 144 CTAs, 256 thr.
// z = limb term: 0 -> hi*hi (w=65536), 1 -> s_hi*W_lo (w=256), 2 -> s_lo*W_hi.
// ---------------------------------------------------------------------------
__global__ __launch_bounds__(NTHREADS, 1)
void gemm_fuse_kernel(const float* __restrict__ V,
                      const float* __restrict__ S,
                      float* __restrict__ out,
                      const __grid_constant__ CUtensorMap map_shi,
                      const __grid_constant__ CUtensorMap map_slo,
                      const __grid_constant__ CUtensorMap map_whi,
                      const __grid_constant__ CUtensorMap map_wlo) {
    extern __shared__ __align__(1024) char smem[];
    const uint32_t smem_base = smem_u32(smem);
    float* rowAcc = (float*)smem;               // 128 floats at offset 0

    const int tid  = threadIdx.x;
    const int wid  = tid >> 5;
    const int lane = tid & 31;
    const int warp_m = wid & 1;                 // 2 x 64 rows
    const int warp_n = wid >> 1;                // 4 x 32 cols

    const int colBase = blockIdx.x * TN;
    const int rowBase = blockIdx.y * TM;
    const int seg     = blockIdx.z;
    const CUtensorMap* mA = (seg == 2) ? &map_slo : &map_shi;
    const CUtensorMap* mB = (seg == 1) ? &map_wlo : &map_whi;
    const float segw = (seg == 0) ? 65536.0f : 256.0f;

    const uint32_t fullBar  = smem_base + SMEM_MBAR_OFF;
    const uint32_t emptyBar = smem_base + SMEM_MBAR_OFF + 32;

    if (tid < TM) rowAcc[tid] = 0.0f;
    if (tid < STAGES)           MBARRIER_INIT(fullBar  + tid * 8, 1);
    else if (tid < 2 * STAGES)  MBARRIER_INIT(emptyBar + (tid - STAGES) * 8, 8);
    __syncthreads();

    if (tid == 0) {
#pragma unroll
        for (int p = 0; p < STAGES - 1; p++) {
            uint32_t mb  = fullBar + p * 8;
            uint32_t dst = smem_base + SMEM_TILES_OFF + p * STAGE_BYTES;
            MBARRIER_EXPECT_TX(mb, STAGE_BYTES);
            tma_load_2d(dst,         mA, p * TK, rowBase, mb);
            tma_load_2d(dst + 16384, mB, p * TK, colBase, mb);
        }
    }

    int acc[4][4][4] = {};                      // [m16 tile][n8 tile][frag] s32
    uint32_t af[2][4][4], bfr[2][2][4];

    const int rowA = lane & 15, colSelA = lane >> 4;
    const int rowB = ((lane >> 4) << 3) + (lane & 7), colSelB = (lane >> 3) & 1;

    for (int it = 0; it < CHUNKS_PER; it++) {
        const int buf = it & 3;

        int nx = it + STAGES - 1;
        if (tid == 0 && nx < CHUNKS_PER) {
            int s = nx & 3;
            if (nx >= STAGES)
                mbar_wait(emptyBar + s * 8, (uint32_t)(((nx >> 2) - 1) & 1));
            uint32_t mb  = fullBar + s * 8;
            uint32_t dst = smem_base + SMEM_TILES_OFF + s * STAGE_BYTES;
            MBARRIER_EXPECT_TX(mb, STAGE_BYTES);
            tma_load_2d(dst,         mA, nx * TK, rowBase, mb);
            tma_load_2d(dst + 16384, mB, nx * TK, colBase, mb);
        }

        mbar_wait(fullBar + buf * 8, (uint32_t)((it >> 2) & 1));

        const uint32_t sA = smem_base + SMEM_TILES_OFF + buf * STAGE_BYTES;
        const uint32_t sB = sA + 16384;

        ldsm_a(sA, warp_m, rowA, colSelA, 0, af[0]);
        ldsm_b(sB, warp_n, rowB, colSelB, 0, bfr[0]);
#pragma unroll
        for (int ks = 0; ks < 4; ks++) {
            const int cur = ks & 1, nxt = cur ^ 1;
            if (ks < 3) {
                ldsm_a(sA, warp_m, rowA, colSelA, ks + 1, af[nxt]);
                ldsm_b(sB, warp_n, rowB, colSelB, ks + 1, bfr[nxt]);
            }
#pragma unroll
            for (int mi = 0; mi < 4; mi++)
#pragma unroll
                for (int nj = 0; nj < 4; nj++) {
                    uint32_t b0 = bfr[cur][nj >> 1][(nj & 1) * 2 + 0];
                    uint32_t b1 = bfr[cur][nj >> 1][(nj & 1) * 2 + 1];
                    MMA_S8(acc[mi][nj], af[cur][mi], b0, b1);
                }
        }

        __syncwarp();
        if (lane == 0) MBARRIER_ARRIVE(emptyBar + buf * 8);
    }

    // --- epilogue 1: C (s32, scale-unwound) . v_x, reduce into logits ---
    const int iBase = (colBase % D) + 32 * warp_n;
    const int nBase = colBase + 32 * warp_n;    // Wcat row index for wscale
    const int kIdx  = colBase / D;

    float rs[4][2] = {};
    float2 wsc[4];
#pragma unroll
    for (int nj = 0; nj < 4; nj++)
        wsc[nj] = *(const float2*)(g_wscale + nBase + 8 * nj + 2 * (lane & 3));

#pragma unroll
    for (int mi = 0; mi < 4; mi++) {
        int r0 = rowBase + 64 * warp_m + 16 * mi + (lane >> 2);
#pragma unroll
        for (int nj = 0; nj < 4; nj++) {
            const float2* v0 = (const float2*)(V + (size_t)r0 * D + iBase
                                               + 8 * nj + 2 * (lane & 3));
            const float2* v1 = (const float2*)(V + (size_t)(r0 + 8) * D + iBase
                                               + 8 * nj + 2 * (lane & 3));
            float2 x0 = *v0, x1 = *v1;
            rs[mi][0] = fmaf((float)acc[mi][nj][0] * wsc[nj].x, x0.x, rs[mi][0]);
            rs[mi][0] = fmaf((float)acc[mi][nj][1] * wsc[nj].y, x0.y, rs[mi][0]);
            rs[mi][1] = fmaf((float)acc[mi][nj][2] * wsc[nj].x, x1.x, rs[mi][1]);
            rs[mi][1] = fmaf((float)acc[mi][nj][3] * wsc[nj].y, x1.y, rs[mi][1]);
        }
    }
#pragma unroll
    for (int mi = 0; mi < 4; mi++)
#pragma unroll
        for (int h = 0; h < 2; h++) {
            rs[mi][h] += __shfl_xor_sync(0xffffffff, rs[mi][h], 1);
            rs[mi][h] += __shfl_xor_sync(0xffffffff, rs[mi][h], 2);
        }
    if ((lane & 3) == 0) {
#pragma unroll
        for (int mi = 0; mi < 4; mi++) {
            int lr = 64 * warp_m + 16 * mi + (lane >> 2);
            atomicAdd(&rowAcc[lr],     rs[mi][0]);
            atomicAdd(&rowAcc[lr + 8], rs[mi][1]);
        }
    }
    __syncthreads();
    if (tid < TM) {
        float val = rowAcc[tid] * segw * g_sscale[rowBase + tid];
        atomicAdd(&g_logits[(rowBase + tid) * 2 + kIdx], val);
    }

    // --- device-wide barrier (144 CTAs, 1/SM: all co-resident) ---
    __threadfence();
    __syncthreads();
    if (tid == 0) {
        atomicAdd(&g_sync, 1);
        while (*(volatile int*)&g_sync != NCTA) { }
    }
    __syncthreads();
    __threadfence();

    // --- epilogue 2: softmax(2 logits) + fused combine, strided over grid ---
    const int ctaLin = (blockIdx.z * gridDim.y + blockIdx.y) * gridDim.x + blockIdx.x;
    const int gt = ctaLin * NTHREADS + tid;
    const int stride = NCTA * NTHREADS;         // 36864
#pragma unroll
    for (int i = 0; i < 3; i++) {
        int idx = gt + i * stride;
        if (idx >= B * D / 4) break;
        int b = idx / (D / 4);
        float l0 = g_logits[b * 2 + 0];
        float l1 = g_logits[b * 2 + 1];
        float mx = fmaxf(l0, l1);
        float e0 = expf(l0 - mx);
        float e1 = expf(l1 - mx);
        float inv = 1.0f / (e0 + e1);
        float wa = e0 * inv;
        float wb = e1 * inv;
        float4 v = ((const float4*)V)[idx];
        float4 s = ((const float4*)S)[idx];
        float4 o;
        o.x = wa * v.x + wb * s.x;
        o.y = wa * v.y + wb * s.y;
        o.z = wa * v.z + wb * s.z;
        o.w = wa * v.w + wb * s.w;
        ((float4*)out)[idx] = o;
    }
}

// ---------------------------------------------------------------------------
// Host: tensormap construction via driver entry point (no -lcuda needed)
// ---------------------------------------------------------------------------
typedef CUresult (*PFN_encodeTiled)(
    CUtensorMap*, CUtensorMapDataType, cuuint32_t, void*,
    const cuuint64_t*, const cuuint64_t*, const cuuint32_t*, const cuuint32_t*,
    CUtensorMapInterleave, CUtensorMapSwizzle, CUtensorMapL2promotion,
    CUtensorMapFloatOOBfill);

static void make_map(PFN_encodeTiled fn, CUtensorMap* m, void* base,
                     unsigned long long rows, unsigned int boxRows) {
    cuuint64_t gd[2] = {(cuuint64_t)D, (cuuint64_t)rows};
    cuuint64_t gs[1] = {(cuuint64_t)D};            // row stride in bytes (int8)
    cuuint32_t bd[2] = {128u, boxRows};            // 128 int8 = 128 B inner box
    cuuint32_t es[2] = {1u, 1u};
    fn(m, CU_TENSOR_MAP_DATA_TYPE_UINT8, 2, base, gd, gs, bd, es,
       CU_TENSOR_MAP_INTERLEAVE_NONE, CU_TENSOR_MAP_SWIZZLE_128B,
       CU_TENSOR_MAP_L2_PROMOTION_L2_128B, CU_TENSOR_MAP_FLOAT_OOB_FILL_NONE);
}

extern "C" void kernel_launch(void* const* d_in, const int* in_sizes, int n_in,
                              void* d_out, int out_size) {
    const float* v_x  = (const float*)d_in[0];
    const float* s_x  = (const float*)d_in[1];
    const float* fc_w = (const float*)d_in[2];
    const float* fc_b = (const float*)d_in[3];
    float* out = (float*)d_out;

    cudaFuncSetAttribute(gemm_fuse_kernel,
                         cudaFuncAttributeMaxDynamicSharedMemorySize, SMEM_TOTAL);

    PFN_encodeTiled encode = nullptr;
    cudaDriverEntryPointQueryResult qres;
    cudaGetDriverEntryPoint("cuTensorMapEncodeTiled", (void**)&encode,
                            cudaEnableDefault, &qres);

    void *p_shi, *p_slo, *p_whi, *p_wlo;
    cudaGetSymbolAddress(&p_shi, g_s_hi);
    cudaGetSymbolAddress(&p_slo, g_s_lo);
    cudaGetSymbolAddress(&p_whi, g_W_hi);
    cudaGetSymbolAddress(&p_wlo, g_W_lo);

    CUtensorMap m_shi, m_slo, m_whi, m_wlo;
    make_map(encode, &m_shi, p_shi, B,    TM);
    make_map(encode, &m_slo, p_slo, B,    TM);
    make_map(encode, &m_whi, p_whi, NTOT, TN);
    make_map(encode, &m_wlo, p_wlo, NTOT, TN);

    // 1) per-row quantization + bias init + sync reset (block per row)
    quant_kernel<<<NTOT + B, 192>>>((const float4*)fc_w, (const float4*)s_x, fc_b);

    // 2) TMA-fed IMMA GEMM + dot-reduce + barrier + softmax/fuse
    dim3 grid(NTOT / TN, B / TM, 3);   // (12, 4, 3) = 144 CTAs
    gemm_fuse_kernel<<<grid, NTHREADS, SMEM_TOTAL>>>(v_x, s_x, out,
                                                     m_shi, m_slo, m_whi, m_wlo);
}

// round 11
// speedup vs baseline: 2.3258x; 2.3258x over previous
#include <cuda_runtime.h>
#include <cuda.h>
#include <cuda_fp16.h>
#include <cstdint>
#include <math.h>

#define D 768
#define B 512
#define NTOT (2 * D)            // 1536 rows of concatenated W

// GEMM tiling: CTA 128x128, 256 threads, warp tile 64x32; TK=64 fp16/stage
#define TM 128
#define TN 128
#define TK 64
#define STAGES 4
#define KSEG 256                // K per CTA (z in 0..2)
#define CHUNKS_PER (KSEG / TK)  // 4
#define NCTA 144                // (12, 4, 3)
#define NTHREADS 256

#define STAGE_BYTES 32768       // A 16KB + B 16KB
#define SMEM_MBAR_OFF 640       // full[4] @640, empty[4] @672
#define SMEM_TILES_OFF 1024
#define SMEM_TOTAL (SMEM_TILES_OFF + STAGES * STAGE_BYTES)   // 132096 -> 1 CTA/SM

// ---------------------------------------------------------------------------
// Device scratch (allocation-free)
// ---------------------------------------------------------------------------
__device__ __half g_s16[B * D];
__device__ __half g_W16[NTOT * D];
__device__ float  g_logits[B * 2];
__device__ int    g_sync;

// ---------------------------------------------------------------------------
// PTX helpers (sm_80/sm_90 base features — legal on plain compute_103)
// ---------------------------------------------------------------------------
__device__ __forceinline__ uint32_t smem_u32(const void* p) {
    uint32_t a;
    asm("{ .reg .u64 t; cvta.to.shared.u64 t, %1; cvt.u32.u64 %0, t; }"
        : "=r"(a) : "l"(p));
    return a;
}

#define SWZ(o) ((o) ^ (((o) >> 3) & 0x70))

#define MBARRIER_INIT(addr, cnt) \
    asm volatile("mbarrier.init.shared.b64 [%0], %1;" :: "r"(addr), "r"(cnt) : "memory")
#define MBARRIER_EXPECT_TX(addr, bytes) \
    asm volatile("mbarrier.arrive.expect_tx.shared.b64 _, [%0], %1;" \
                 :: "r"(addr), "r"(bytes) : "memory")
#define MBARRIER_ARRIVE(addr) \
    asm volatile("mbarrier.arrive.shared.b64 _, [%0];" :: "r"(addr) : "memory")

__device__ __forceinline__ void mbar_wait(uint32_t mbar, uint32_t parity) {
    uint32_t done;
    asm volatile("{\n\t.reg .pred p;\n\t"
                 "mbarrier.try_wait.parity.acquire.cta.shared::cta.b64 p, [%1], %2;\n\t"
                 "selp.b32 %0, 1, 0, p;\n\t}"
                 : "=r"(done) : "r"(mbar), "r"(parity) : "memory");
    if (!done) {
        asm volatile("{\n\t.reg .pred P1;\n\t"
                     "WL_%=:\n\t"
                     "mbarrier.try_wait.parity.acquire.cta.shared::cta.b64 P1, [%0], %1, 0x989680;\n\t"
                     "@P1 bra.uni WD_%=;\n\t"
                     "bra.uni WL_%=;\n\t"
                     "WD_%=:\n\t}"
                     :: "r"(mbar), "r"(parity) : "memory");
    }
}

__device__ __forceinline__ void tma_load_2d(uint32_t dst, const CUtensorMap* map,
                                            int x, int y, uint32_t mbar) {
    asm volatile("cp.async.bulk.tensor.2d.shared::cta.global.tile.mbarrier::complete_tx::bytes "
                 "[%0], [%1, {%2, %3}], [%4];"
                 :: "r"(dst), "l"(map), "r"(x), "r"(y), "r"(mbar) : "memory");
}

#define LDSM_X4(r, addr) \
    asm volatile("ldmatrix.sync.aligned.m8n8.x4.shared.b16 {%0,%1,%2,%3}, [%4];" \
                 : "=r"((r)[0]), "=r"((r)[1]), "=r"((r)[2]), "=r"((r)[3]) \
                 : "r"(addr))

// fp16 MMA, fp32 accumulate
#define MMA_F16(d, a, b0, b1) \
    asm volatile("mma.sync.aligned.m16n8k16.row.col.f32.f16.f16.f32 " \
                 "{%0,%1,%2,%3}, {%4,%5,%6,%7}, {%8,%9}, {%0,%1,%2,%3};" \
                 : "+f"((d)[0]), "+f"((d)[1]), "+f"((d)[2]), "+f"((d)[3]) \
                 : "r"((a)[0]), "r"((a)[1]), "r"((a)[2]), "r"((a)[3]), \
                   "r"(b0), "r"(b1))

// ---------------------------------------------------------------------------
// Kernel 1: fp32 -> fp16 convert (8 floats/thread, 128-bit stores).
// Also: logits = bias, g_sync = 0.
// ---------------------------------------------------------------------------
__global__ __launch_bounds__(256)
void quant_kernel(const float4* __restrict__ W4p,
                  const float4* __restrict__ S4p,
                  const float* __restrict__ fc_b) {
    const int WP = NTOT * D / 8;   // 147456
    const int SP = B * D / 8;      // 49152
    int g = blockIdx.x * blockDim.x + threadIdx.x;

    if (g == 0) g_sync = 0;
    if (g < B * 2) g_logits[g] = fc_b[g & 1];
    if (g >= WP + SP) return;

    float4 x0, x1;
    __half* dst;
    int e;
    if (g < WP) { x0 = W4p[2 * g]; x1 = W4p[2 * g + 1]; dst = g_W16; e = g * 8; }
    else {
        int q = g - WP;
        x0 = S4p[2 * q]; x1 = S4p[2 * q + 1]; dst = g_s16; e = q * 8;
    }

    __half2 h[4];
    h[0] = __float22half2_rn(make_float2(x0.x, x0.y));
    h[1] = __float22half2_rn(make_float2(x0.z, x0.w));
    h[2] = __float22half2_rn(make_float2(x1.x, x1.y));
    h[3] = __float22half2_rn(make_float2(x1.z, x1.w));
    *(uint4*)(dst + e) = make_uint4(*(uint32_t*)&h[0], *(uint32_t*)&h[1],
                                    *(uint32_t*)&h[2], *(uint32_t*)&h[3]);
}

// ---------------------------------------------------------------------------
// Fragment loaders (SW128-swizzled LDSM)
// ---------------------------------------------------------------------------
__device__ __forceinline__ void ldsm_a(uint32_t sA, int warp_m, int rowA,
                                       int colSelA, int ks, uint32_t af[4][4]) {
#pragma unroll
    for (int mi = 0; mi < 4; mi++) {
        uint32_t addr = sA + SWZ((64 * warp_m + 16 * mi + rowA) * 128
                                 + (2 * ks + colSelA) * 16);
        LDSM_X4(af[mi], addr);
    }
}
__device__ __forceinline__ void ldsm_b(uint32_t sB, int warp_n, int rowB,
                                       int colSelB, int ks, uint32_t bfr[2][4]) {
#pragma unroll
    for (int q = 0; q < 2; q++) {
        uint32_t addr = sB + SWZ((32 * warp_n + 16 * q + rowB) * 128
                                 + (2 * ks + colSelB) * 16);
        LDSM_X4(bfr[q], addr);
    }
}

// ---------------------------------------------------------------------------
// Kernel 2: TMA-fed fp16 HMMA GEMM (single pass, K-split across z) +
// v-dot reduce + device-wide barrier + softmax/fuse.
// Grid (12, 4, 3) = 144 CTAs, 256 threads. z = K segment (256 wide).
// Partial C tiles (K-segment sums) dot with v and sum linearly into logits.
// ---------------------------------------------------------------------------
__global__ __launch_bounds__(NTHREADS, 1)
void gemm_fuse_kernel(const float* __restrict__ V,
                      const float* __restrict__ S,
                      float* __restrict__ out,
                      const __grid_constant__ CUtensorMap map_s,
                      const __grid_constant__ CUtensorMap map_w) {
    extern __shared__ __align__(1024) char smem[];
    const uint32_t smem_base = smem_u32(smem);
    float* rowAcc = (float*)smem;               // 128 floats at offset 0

    const int tid  = threadIdx.x;
    const int wid  = tid >> 5;
    const int lane = tid & 31;
    const int warp_m = wid & 1;                 // 2 x 64 rows
    const int warp_n = wid >> 1;                // 4 x 32 cols

    const int colBase = blockIdx.x * TN;
    const int rowBase = blockIdx.y * TM;
    const int kOff0   = blockIdx.z * KSEG;

    const uint32_t fullBar  = smem_base + SMEM_MBAR_OFF;
    const uint32_t emptyBar = smem_base + SMEM_MBAR_OFF + 32;

    if (tid < TM) rowAcc[tid] = 0.0f;
    if (tid < STAGES)           MBARRIER_INIT(fullBar  + tid * 8, 1);
    else if (tid < 2 * STAGES)  MBARRIER_INIT(emptyBar + (tid - STAGES) * 8, 8);
    __syncthreads();

    if (tid == 0) {
#pragma unroll
        for (int p = 0; p < STAGES - 1; p++) {
            uint32_t mb  = fullBar + p * 8;
            uint32_t dst = smem_base + SMEM_TILES_OFF + p * STAGE_BYTES;
            MBARRIER_EXPECT_TX(mb, STAGE_BYTES);
            tma_load_2d(dst,         &map_s, kOff0 + p * TK, rowBase, mb);
            tma_load_2d(dst + 16384, &map_w, kOff0 + p * TK, colBase, mb);
        }
    }

    float acc[4][4][4] = {};                    // [m16 tile][n8 tile][frag]
    uint32_t af[2][4][4], bfr[2][2][4];

    const int rowA = lane & 15, colSelA = lane >> 4;
    const int rowB = ((lane >> 4) << 3) + (lane & 7), colSelB = (lane >> 3) & 1;

    for (int it = 0; it < CHUNKS_PER; it++) {
        const int buf = it & 3;

        int nx = it + STAGES - 1;
        if (tid == 0 && nx < CHUNKS_PER) {
            int s = nx & 3;
            if (nx >= STAGES)
                mbar_wait(emptyBar + s * 8, (uint32_t)(((nx >> 2) - 1) & 1));
            uint32_t mb  = fullBar + s * 8;
            uint32_t dst = smem_base + SMEM_TILES_OFF + s * STAGE_BYTES;
            MBARRIER_EXPECT_TX(mb, STAGE_BYTES);
            tma_load_2d(dst,         &map_s, kOff0 + nx * TK, rowBase, mb);
            tma_load_2d(dst + 16384, &map_w, kOff0 + nx * TK, colBase, mb);
        }

        mbar_wait(fullBar + buf * 8, (uint32_t)((it >> 2) & 1));

        const uint32_t sA = smem_base + SMEM_TILES_OFF + buf * STAGE_BYTES;
        const uint32_t sB = sA + 16384;

        ldsm_a(sA, warp_m, rowA, colSelA, 0, af[0]);
        ldsm_b(sB, warp_n, rowB, colSelB, 0, bfr[0]);
#pragma unroll
        for (int ks = 0; ks < 4; ks++) {
            const int cur = ks & 1, nxt = cur ^ 1;
            if (ks < 3) {
                ldsm_a(sA, warp_m, rowA, colSelA, ks + 1, af[nxt]);
                ldsm_b(sB, warp_n, rowB, colSelB, ks + 1, bfr[nxt]);
            }
#pragma unroll
            for (int mi = 0; mi < 4; mi++)
#pragma unroll
                for (int nj = 0; nj < 4; nj++) {
                    uint32_t b0 = bfr[cur][nj >> 1][(nj & 1) * 2 + 0];
                    uint32_t b1 = bfr[cur][nj >> 1][(nj & 1) * 2 + 1];
                    MMA_F16(acc[mi][nj], af[cur][mi], b0, b1);
                }
        }

        __syncwarp();
        if (lane == 0) MBARRIER_ARRIVE(emptyBar + buf * 8);
    }

    // --- epilogue 1: partial C . v_x, reduce into logits ---
    const int iBase = (colBase % D) + 32 * warp_n;
    const int kIdx  = colBase / D;

    float rs[4][2] = {};
#pragma unroll
    for (int mi = 0; mi < 4; mi++) {
        int r0 = rowBase + 64 * warp_m + 16 * mi + (lane >> 2);
#pragma unroll
        for (int nj = 0; nj < 4; nj++) {
            const float2* v0 = (const float2*)(V + (size_t)r0 * D + iBase
                                               + 8 * nj + 2 * (lane & 3));
            const float2* v1 = (const float2*)(V + (size_t)(r0 + 8) * D + iBase
                                               + 8 * nj + 2 * (lane & 3));
            float2 x0 = *v0, x1 = *v1;
            rs[mi][0] = fmaf(acc[mi][nj][0], x0.x, rs[mi][0]);
            rs[mi][0] = fmaf(acc[mi][nj][1], x0.y, rs[mi][0]);
            rs[mi][1] = fmaf(acc[mi][nj][2], x1.x, rs[mi][1]);
            rs[mi][1] = fmaf(acc[mi][nj][3], x1.y, rs[mi][1]);
        }
    }
#pragma unroll
    for (int mi = 0; mi < 4; mi++)
#pragma unroll
        for (int h = 0; h < 2; h++) {
            rs[mi][h] += __shfl_xor_sync(0xffffffff, rs[mi][h], 1);
            rs[mi][h] += __shfl_xor_sync(0xffffffff, rs[mi][h], 2);
        }
    if ((lane & 3) == 0) {
#pragma unroll
        for (int mi = 0; mi < 4; mi++) {
            int lr = 64 * warp_m + 16 * mi + (lane >> 2);
            atomicAdd(&rowAcc[lr],     rs[mi][0]);
            atomicAdd(&rowAcc[lr + 8], rs[mi][1]);
        }
    }
    __syncthreads();
    if (tid < TM)
        atomicAdd(&g_logits[(rowBase + tid) * 2 + kIdx], rowAcc[tid]);

    // --- device-wide barrier (144 CTAs, 1/SM: all co-resident) ---
    __threadfence();
    __syncthreads();
    if (tid == 0) {
        atomicAdd(&g_sync, 1);
        while (*(volatile int*)&g_sync != NCTA) { }
    }
    __syncthreads();
    __threadfence();

    // --- epilogue 2: softmax(2 logits) + fused combine, strided over grid ---
    const int ctaLin = (blockIdx.z * gridDim.y + blockIdx.y) * gridDim.x + blockIdx.x;
    const int gt = ctaLin * NTHREADS + tid;
    const int stride = NCTA * NTHREADS;         // 36864
#pragma unroll
    for (int i = 0; i < 3; i++) {
        int idx = gt + i * stride;
        if (idx >= B * D / 4) break;
        int b = idx / (D / 4);
        float l0 = g_logits[b * 2 + 0];
        float l1 = g_logits[b * 2 + 1];
        float mx = fmaxf(l0, l1);
        float e0 = expf(l0 - mx);
        float e1 = expf(l1 - mx);
        float inv = 1.0f / (e0 + e1);
        float wa = e0 * inv;
        float wb = e1 * inv;
        float4 v = ((const float4*)V)[idx];
        float4 s = ((const float4*)S)[idx];
        float4 o;
        o.x = wa * v.x + wb * s.x;
        o.y = wa * v.y + wb * s.y;
        o.z = wa * v.z + wb * s.z;
        o.w = wa * v.w + wb * s.w;
        ((float4*)out)[idx] = o;
    }
}

// ---------------------------------------------------------------------------
// Host: tensormap construction via driver entry point (no -lcuda needed)
// ---------------------------------------------------------------------------
typedef CUresult (*PFN_encodeTiled)(
    CUtensorMap*, CUtensorMapDataType, cuuint32_t, void*,
    const cuuint64_t*, const cuuint64_t*, const cuuint32_t*, const cuuint32_t*,
    CUtensorMapInterleave, CUtensorMapSwizzle, CUtensorMapL2promotion,
    CUtensorMapFloatOOBfill);

static void make_map(PFN_encodeTiled fn, CUtensorMap* m, void* base,
                     unsigned long long rows, unsigned int boxRows) {
    cuuint64_t gd[2] = {(cuuint64_t)D, (cuuint64_t)rows};
    cuuint64_t gs[1] = {(cuuint64_t)(D * 2)};     // row stride in bytes (fp16)
    cuuint32_t bd[2] = {64u, boxRows};            // 64 fp16 = 128 B inner box
    cuuint32_t es[2] = {1u, 1u};
    fn(m, CU_TENSOR_MAP_DATA_TYPE_FLOAT16, 2, base, gd, gs, bd, es,
       CU_TENSOR_MAP_INTERLEAVE_NONE, CU_TENSOR_MAP_SWIZZLE_128B,
       CU_TENSOR_MAP_L2_PROMOTION_L2_128B, CU_TENSOR_MAP_FLOAT_OOB_FILL_NONE);
}

extern "C" void kernel_launch(void* const* d_in, const int* in_sizes, int n_in,
                              void* d_out, int out_size) {
    const float* v_x  = (const float*)d_in[0];
    const float* s_x  = (const float*)d_in[1];
    const float* fc_w = (const float*)d_in[2];
    const float* fc_b = (const float*)d_in[3];
    float* out = (float*)d_out;

    cudaFuncSetAttribute(gemm_fuse_kernel,
                         cudaFuncAttributeMaxDynamicSharedMemorySize, SMEM_TOTAL);

    PFN_encodeTiled encode = nullptr;
    cudaDriverEntryPointQueryResult qres;
    cudaGetDriverEntryPoint("cuTensorMapEncodeTiled", (void**)&encode,
                            cudaEnableDefault, &qres);

    void *p_s16, *p_W16;
    cudaGetSymbolAddress(&p_s16, g_s16);
    cudaGetSymbolAddress(&p_W16, g_W16);

    CUtensorMap m_s, m_w;
    make_map(encode, &m_s, p_s16, B,    TM);
    make_map(encode, &m_w, p_W16, NTOT, TN);

    // 1) fp16 convert + bias init + sync reset
    quant_kernel<<<768, 256>>>((const float4*)fc_w, (const float4*)s_x, fc_b);

    // 2) single-pass TMA-fed fp16 HMMA GEMM + dot-reduce + barrier + fuse
    dim3 grid(NTOT / TN, B / TM, 3);   // (12, 4, 3) = 144 CTAs, K-split
    gemm_fuse_kernel<<<grid, NTHREADS, SMEM_TOTAL>>>(v_x, s_x, out, m_s, m_w);
}